// round 8
// baseline (speedup 1.0000x reference)
#include <cuda_runtime.h>
#include <math.h>
#include <float.h>

#define BB 8
#define NN 4096
#define NP (NN / 2)       // element pairs
#define RCTA 32           // rows per CTA
#define NCTA (NN / RCTA)  // 128 CTAs per batch

static __device__ __constant__ float kEPS = 1e-5f;
static __device__ __constant__ float kF2  = 2.8853900817779268f; // FACT * log2(e)
#define SKIP_LOG2 35.0f

// Scratch (device globals; fully overwritten every run — no init/atomics)
__device__ float g_pcn[BB][3][NN];
__device__ float g_dist[BB][NN];
__device__ float g_dpart[BB][NCTA];
__device__ float g_mpart[BB][8][16];

typedef unsigned long long u64;

__device__ __forceinline__ float frcp(float x) {
    float r; asm("rcp.approx.f32 %0, %1;" : "=f"(r) : "f"(x)); return r;
}
__device__ __forceinline__ float fex2(float x) {
    float r; asm("ex2.approx.f32 %0, %1;" : "=f"(r) : "f"(x)); return r;
}
__device__ __forceinline__ u64 pk2(float lo, float hi) {
    u64 r; asm("mov.b64 %0, {%1, %2};" : "=l"(r) : "f"(lo), "f"(hi)); return r;
}
__device__ __forceinline__ void upk2(u64 v, float& lo, float& hi) {
    asm("mov.b64 {%0, %1}, %2;" : "=f"(lo), "=f"(hi) : "l"(v));
}
__device__ __forceinline__ u64 fma2(u64 a, u64 b, u64 c) {
    u64 d; asm("fma.rn.f32x2 %0, %1, %2, %3;" : "=l"(d) : "l"(a), "l"(b), "l"(c)); return d;
}
__device__ __forceinline__ u64 mul2(u64 a, u64 b) {
    u64 d; asm("mul.rn.f32x2 %0, %1, %2;" : "=l"(d) : "l"(a), "l"(b)); return d;
}
__device__ __forceinline__ u64 add2(u64 a, u64 b) {
    u64 d; asm("add.rn.f32x2 %0, %1, %2;" : "=l"(d) : "l"(a), "l"(b)); return d;
}

// ---------------------------------------------------------------------------
// Kernel 1: rows. Two-pass, 4 rows/warp, vote-skip + software-pipelined pass2.
// SMEM: sXY[p] = {pk2(x0,x1), pk2(y0,y1)}, sZR[p] = {pk2(z0,z1), pk2(r0,r1)}
// d' = r2 - 2*p1.p2  (chain: fma2(nx,x, fma2(ny,y, fma2(nz,z, r2))) minus rA)
// Actually d' excludes rA only; r2 stays in smem operand:
//   d' = fma2(nz,z, fma2(ny,y, fma2(nx,x, r01)));   d = d' + rA
// ---------------------------------------------------------------------------
__global__ void __launch_bounds__(256, 3)
cpnet_rows(const float* __restrict__ pc1, const float* __restrict__ pc2) {
    extern __shared__ ulonglong2 smem[];
    ulonglong2* sXY = smem;        // 32KB
    ulonglong2* sZR = smem + NP;   // 32KB
    const int b = blockIdx.y;
    const float* p2 = pc2 + (size_t)b * 4 * NN;
    const float* p1 = pc1 + (size_t)b * 4 * NN;

    {
        const float2* px = (const float2*)p2;
        const float2* py = (const float2*)(p2 + NN);
        const float2* pz = (const float2*)(p2 + 2 * NN);
        for (int i = threadIdx.x; i < NP; i += blockDim.x) {
            float2 x = px[i], y = py[i], z = pz[i];
            float r0 = fmaf(z.x, z.x, fmaf(y.x, y.x, x.x * x.x));
            float r1 = fmaf(z.y, z.y, fmaf(y.y, y.y, x.y * x.y));
            sXY[i] = make_ulonglong2(pk2(x.x, x.y), pk2(y.x, y.y));
            sZR[i] = make_ulonglong2(pk2(z.x, z.y), pk2(r0, r1));
        }
    }
    __syncthreads();

    const int warp = threadIdx.x >> 5;
    const int lane = threadIdx.x & 31;
    const int n0 = blockIdx.x * RCTA + (warp << 2);  // 4 consecutive rows

    float rA[4];
    u64 nx2[4], ny2[4], nz2[4];
    #pragma unroll
    for (int r = 0; r < 4; ++r) {
        float x1 = p1[n0 + r];
        float y1 = p1[NN + n0 + r];
        float z1 = p1[2 * NN + n0 + r];
        rA[r] = fmaf(z1, z1, fmaf(y1, y1, x1 * x1));
        nx2[r] = pk2(-2.f * x1, -2.f * x1);
        ny2[r] = pk2(-2.f * y1, -2.f * y1);
        nz2[r] = pk2(-2.f * z1, -2.f * z1);
    }

    // ---- Pass 1: min d' per row (d = d' + rA, monotone) ----
    float dm[4] = {FLT_MAX, FLT_MAX, FLT_MAX, FLT_MAX};
    #pragma unroll 4
    for (int p = lane; p < NP; p += 32) {
        ulonglong2 xy = sXY[p];
        ulonglong2 zr = sZR[p];
        #pragma unroll
        for (int r = 0; r < 4; ++r) {
            u64 d = fma2(nz2[r], zr.x, fma2(ny2[r], xy.y,
                         fma2(nx2[r], xy.x, zr.y)));
            float lo, hi; upk2(d, lo, hi);
            dm[r] = fminf(dm[r], fminf(lo, hi));
        }
    }
    #pragma unroll
    for (int o = 16; o; o >>= 1)
        #pragma unroll
        for (int r = 0; r < 4; ++r)
            dm[r] = fminf(dm[r], __shfl_xor_sync(0xffffffffu, dm[r], o));

    float cc[4], thrP[4];
    #pragma unroll
    for (int r = 0; r < 4; ++r) {
        float dmin = dm[r] + rA[r];
        cc[r] = kF2 * frcp(fmaxf(dmin, kEPS));
        thrP[r] = (cc[r] > SKIP_LOG2) ? kF2 * frcp(cc[r] - SKIP_LOG2) - rA[r]
                                      : FLT_MAX;
    }

    // ---- Pass 2: software-pipelined, vote-skip ----
    u64 Zk[4] = {0, 0, 0, 0}, ax[4] = {0, 0, 0, 0};
    u64 ay[4] = {0, 0, 0, 0}, az[4] = {0, 0, 0, 0};
    {
        int p = lane;
        ulonglong2 xy = sXY[p];
        ulonglong2 zr = sZR[p];
        #pragma unroll 1
        for (int it = 0; it < NP / 32; ++it) {
            const int pn = (p + 32) & (NP - 1);       // wrap: valid, branchless
            const ulonglong2 xyn = sXY[pn];
            const ulonglong2 zrn = sZR[pn];

            float dlo[4], dhi[4];
            bool f = false;
            #pragma unroll
            for (int r = 0; r < 4; ++r) {
                u64 d = fma2(nz2[r], zr.x, fma2(ny2[r], xy.y,
                             fma2(nx2[r], xy.x, zr.y)));
                upk2(d, dlo[r], dhi[r]);
                f |= (fminf(dlo[r], dhi[r]) <= thrP[r]);
            }
            if (__any_sync(0xffffffffu, f)) {
                #pragma unroll
                for (int r = 0; r < 4; ++r) {
                    float i0 = frcp(fmaxf(dlo[r] + rA[r], kEPS));
                    float i1 = frcp(fmaxf(dhi[r] + rA[r], kEPS));
                    float g0 = fmaf(i0, kF2, -cc[r]);
                    float g1 = fmaf(i1, kF2, -cc[r]);
                    u64 w = pk2(fex2(g0), fex2(g1));
                    Zk[r] = add2(Zk[r], w);
                    ax[r] = fma2(w, xy.x, ax[r]);
                    ay[r] = fma2(w, xy.y, ay[r]);
                    az[r] = fma2(w, zr.x, az[r]);
                }
            }
            xy = xyn; zr = zrn; p = pn;
        }
    }

    float Zs[4], vx[4], vy[4], vz[4];
    #pragma unroll
    for (int r = 0; r < 4; ++r) {
        float lo, hi;
        upk2(Zk[r], lo, hi); Zs[r] = lo + hi;
        upk2(ax[r], lo, hi); vx[r] = lo + hi;
        upk2(ay[r], lo, hi); vy[r] = lo + hi;
        upk2(az[r], lo, hi); vz[r] = lo + hi;
    }
    #pragma unroll
    for (int o = 16; o; o >>= 1) {
        #pragma unroll
        for (int r = 0; r < 4; ++r) {
            Zs[r] += __shfl_xor_sync(0xffffffffu, Zs[r], o);
            vx[r] += __shfl_xor_sync(0xffffffffu, vx[r], o);
            vy[r] += __shfl_xor_sync(0xffffffffu, vy[r], o);
            vz[r] += __shfl_xor_sync(0xffffffffu, vz[r], o);
        }
    }

    __shared__ float sds[8];
    if (lane == 0) {
        float dsum = 0.f;
        #pragma unroll
        for (int r = 0; r < 4; ++r) {
            float x1 = p1[n0 + r];                 // reloaded, not kept live
            float y1 = p1[NN + n0 + r];
            float z1 = p1[2 * NN + n0 + r];
            float rz = 1.0f / Zs[r];
            float q0 = vx[r] * rz, q1 = vy[r] * rz, q2 = vz[r] * rz;
            float dx = x1 - q0, dy = y1 - q1, dz = z1 - q2;
            float dist = sqrtf(dx * dx + dy * dy + dz * dz);
            g_pcn[b][0][n0 + r] = q0;
            g_pcn[b][1][n0 + r] = q1;
            g_pcn[b][2][n0 + r] = q2;
            g_dist[b][n0 + r] = dist;
            dsum += dist;
        }
        sds[warp] = dsum;
    }
    __syncthreads();
    if (threadIdx.x == 0) {
        float s = 0.f;
        #pragma unroll
        for (int i = 0; i < 8; ++i) s += sds[i];
        g_dpart[b][blockIdx.x] = s;
    }
}

// ---------------------------------------------------------------------------
// Kernel 2: moments. grid (8 slices, BB batches) x 256. Mean from g_dpart,
// 16 uncentered moments over the slice's 512 elements -> g_mpart.
// ---------------------------------------------------------------------------
__global__ void __launch_bounds__(256)
cpnet_moments(const float* __restrict__ pc1) {
    const int b = blockIdx.y;
    const int slice = blockIdx.x;
    const float* p1 = pc1 + (size_t)b * 4 * NN;
    const int tid = threadIdx.x;
    const int lane = tid & 31;
    const int w = tid >> 5;  // 8 warps

    __shared__ float smW[8];
    __shared__ float smP[8][16];

    // mean from 128 CTA partials
    float v = (tid < NCTA) ? g_dpart[b][tid] : 0.f;
    #pragma unroll
    for (int o = 16; o; o >>= 1) v += __shfl_xor_sync(0xffffffffu, v, o);
    if (lane == 0) smW[w] = v;
    __syncthreads();
    double ms = 0.0;
    #pragma unroll
    for (int i = 0; i < 8; ++i) ms += (double)smW[i];
    const float mean = (float)(ms * (1.0 / (double)NN));

    float P[16];
    #pragma unroll
    for (int i = 0; i < 16; ++i) P[i] = 0.f;
    #pragma unroll
    for (int k = 0; k < 2; ++k) {
        int n = slice * 512 + k * 256 + tid;
        float dist = g_dist[b][n];
        float z = (dist - mean - kEPS) * 1e10f;
        float ind = 1.0f / (1.0f + __expf(z));
        float axx = p1[n], ayy = p1[NN + n], azz = p1[2 * NN + n];
        float bx = g_pcn[b][0][n], by = g_pcn[b][1][n], bz = g_pcn[b][2][n];
        float iax = ind * axx, iay = ind * ayy, iaz = ind * azz;
        P[0] += ind;
        P[1] += iax; P[2] += iay; P[3] += iaz;
        P[4] += ind * bx; P[5] += ind * by; P[6] += ind * bz;
        P[7]  += iax * bx; P[8]  += iax * by; P[9]  += iax * bz;
        P[10] += iay * bx; P[11] += iay * by; P[12] += iay * bz;
        P[13] += iaz * bx; P[14] += iaz * by; P[15] += iaz * bz;
    }
    #pragma unroll
    for (int o = 16; o; o >>= 1)
        #pragma unroll
        for (int i = 0; i < 16; ++i)
            P[i] += __shfl_xor_sync(0xffffffffu, P[i], o);
    if (lane == 0) {
        #pragma unroll
        for (int i = 0; i < 16; ++i) smP[w][i] = P[i];
    }
    __syncthreads();
    if (w == 0 && lane < 16) {
        float s = 0.f;
        #pragma unroll
        for (int ww = 0; ww < 8; ++ww) s += smP[ww][lane];
        g_mpart[b][slice][lane] = s;
    }
}

// ---------------------------------------------------------------------------
// Kernel 3: SVD tail per batch.
// ---------------------------------------------------------------------------
__global__ void cpnet_svd(float* __restrict__ out) {
    const int b = blockIdx.x;
    if (threadIdx.x != 0) return;

    double S[16];
    #pragma unroll
    for (int i = 0; i < 16; ++i) {
        double s = 0.0;
        #pragma unroll
        for (int sl = 0; sl < 8; ++sl) s += (double)g_mpart[b][sl][i];
        S[i] = s;
    }

    const double sw = S[0];
    const double inv_sw = 1.0 / sw;
    float c1v[3] = {(float)(S[1] * inv_sw), (float)(S[2] * inv_sw), (float)(S[3] * inv_sw)};
    float c2v[3] = {(float)(S[4] * inv_sw), (float)(S[5] * inv_sw), (float)(S[6] * inv_sw)};
    float H[3][3];
    #pragma unroll
    for (int i = 0; i < 3; ++i)
        #pragma unroll
        for (int j = 0; j < 3; ++j)
            H[i][j] = (float)(S[7 + i * 3 + j] - S[1 + i] * S[4 + j] * inv_sw);

    float G[3][3];
    #pragma unroll
    for (int i = 0; i < 3; ++i)
        #pragma unroll
        for (int j = 0; j < 3; ++j)
            G[i][j] = H[0][i] * H[0][j] + H[1][i] * H[1][j] + H[2][i] * H[2][j];
    float V[3][3] = {{1, 0, 0}, {0, 1, 0}, {0, 0, 1}};
    const int PP[3] = {0, 0, 1}, QQ[3] = {1, 2, 2};
    #pragma unroll
    for (int it = 0; it < 18; ++it) {
        int p = PP[it % 3], q = QQ[it % 3];
        float apq = G[p][q];
        if (fabsf(apq) > 1e-25f) {
            float theta = (G[q][q] - G[p][p]) / (2.0f * apq);
            float t = copysignf(1.0f, theta) / (fabsf(theta) + sqrtf(theta * theta + 1.0f));
            float c = rsqrtf(t * t + 1.0f);
            float sn = t * c;
            #pragma unroll
            for (int k = 0; k < 3; ++k) {
                float gkp = G[k][p], gkq = G[k][q];
                G[k][p] = c * gkp - sn * gkq;
                G[k][q] = sn * gkp + c * gkq;
            }
            #pragma unroll
            for (int k = 0; k < 3; ++k) {
                float gpk = G[p][k], gqk = G[q][k];
                G[p][k] = c * gpk - sn * gqk;
                G[q][k] = sn * gpk + c * gqk;
            }
            #pragma unroll
            for (int k = 0; k < 3; ++k) {
                float vkp = V[k][p], vkq = V[k][q];
                V[k][p] = c * vkp - sn * vkq;
                V[k][q] = sn * vkp + c * vkq;
            }
        }
    }
    float ev[3] = {G[0][0], G[1][1], G[2][2]};
    #pragma unroll
    for (int a = 0; a < 2; ++a)
        #pragma unroll
        for (int bc = 1; bc < 3; ++bc)
            if (bc > a && ev[bc] > ev[a]) {
                float te = ev[a]; ev[a] = ev[bc]; ev[bc] = te;
                #pragma unroll
                for (int k = 0; k < 3; ++k) {
                    float tv = V[k][a]; V[k][a] = V[k][bc]; V[k][bc] = tv;
                }
            }
    float U[3][3];
    #pragma unroll
    for (int j = 0; j < 3; ++j) {
        float sig = sqrtf(fmaxf(ev[j], 0.f));
        float inv = (sig > 1e-20f) ? (1.0f / sig) : 0.f;
        #pragma unroll
        for (int i = 0; i < 3; ++i)
            U[i][j] = (H[i][0] * V[0][j] + H[i][1] * V[1][j] + H[i][2] * V[2][j]) * inv;
    }
    auto det3 = [](float M[3][3]) {
        return M[0][0] * (M[1][1] * M[2][2] - M[1][2] * M[2][1])
             - M[0][1] * (M[1][0] * M[2][2] - M[1][2] * M[2][0])
             + M[0][2] * (M[1][0] * M[2][1] - M[1][1] * M[2][0]);
    };
    float sign = (det3(U) * det3(V) < 0.f) ? -1.f : 1.f;
    V[0][2] *= sign; V[1][2] *= sign; V[2][2] *= sign;
    float R[3][3];
    #pragma unroll
    for (int i = 0; i < 3; ++i)
        #pragma unroll
        for (int j = 0; j < 3; ++j)
            R[i][j] = V[i][0] * U[j][0] + V[i][1] * U[j][1] + V[i][2] * U[j][2];
    float tt[3];
    #pragma unroll
    for (int i = 0; i < 3; ++i)
        tt[i] = c2v[i] - (R[i][0] * c1v[0] + R[i][1] * c1v[1] + R[i][2] * c1v[2]);

    float* T = out + b * 16;
    #pragma unroll
    for (int i = 0; i < 3; ++i) {
        T[i * 4 + 0] = R[i][0];
        T[i * 4 + 1] = R[i][1];
        T[i * 4 + 2] = R[i][2];
        T[i * 4 + 3] = tt[i];
    }
    T[12] = 0.f; T[13] = 0.f; T[14] = 0.f; T[15] = 1.f;

    auto sgn = [](float x) { return x >= 0.f ? 1.f : -1.f; };
    float qw = 0.5f * sqrtf(fmaxf(1.f + R[0][0] + R[1][1] + R[2][2], 1e-12f));
    float qx = 0.5f * sqrtf(fmaxf(1.f + R[0][0] - R[1][1] - R[2][2], 1e-12f)) * sgn(R[2][1] - R[1][2]);
    float qy = 0.5f * sqrtf(fmaxf(1.f - R[0][0] + R[1][1] - R[2][2], 1e-12f)) * sgn(R[0][2] - R[2][0]);
    float qz = 0.5f * sqrtf(fmaxf(1.f - R[0][0] - R[1][1] + R[2][2], 1e-12f)) * sgn(R[1][0] - R[0][1]);
    float* qo = out + BB * 16 + b * 4;
    qo[0] = qw; qo[1] = qx; qo[2] = qy; qo[3] = qz;
    float* to = out + BB * 16 + BB * 4 + b * 3;
    to[0] = tt[0]; to[1] = tt[1]; to[2] = tt[2];
}

// ---------------------------------------------------------------------------
extern "C" void kernel_launch(void* const* d_in, const int* in_sizes, int n_in,
                              void* d_out, int out_size) {
    const float* pc1 = (const float*)d_in[0];
    const float* pc2 = (const float*)d_in[1];
    float* out = (float*)d_out;

    cudaFuncSetAttribute(cpnet_rows, cudaFuncAttributeMaxDynamicSharedMemorySize,
                         2 * NP * (int)sizeof(ulonglong2));

    dim3 grid(NCTA, BB);  // 128 x 8 = 1024 CTAs, 32 rows each (4 per warp)
    cpnet_rows<<<grid, 256, 2 * NP * sizeof(ulonglong2)>>>(pc1, pc2);
    dim3 mgrid(8, BB);    // 8 slices x 8 batches
    cpnet_moments<<<mgrid, 256>>>(pc1);
    cpnet_svd<<<BB, 32>>>(out);
}

// round 9
// speedup vs baseline: 1.4717x; 1.4717x over previous
#include <cuda_runtime.h>
#include <math.h>
#include <float.h>

#define BB 8
#define NN 4096
#define GC 16                 // grid cells per axis
#define NCELL (GC * GC * GC)  // 4096
#define RPC 8                 // rows per CTA (1 row per warp)
#define RCTAS (NN / RPC)      // 512 row-CTAs per batch

static __device__ __constant__ float kEPS = 1e-5f;
static __device__ __constant__ float kF2  = 2.8853900817779268f; // FACT*log2(e)

// Scratch (device globals; fully overwritten every run)
__device__ float4 g_spts[BB][NN];             // cell-sorted pc2 points
__device__ int    g_cellstart[BB][NCELL + 1];
__device__ float  g_grid[BB][8];              // mbx,mby,mbz,icwx,icwy,icwz,minw
__device__ float  g_pcn[BB][3][NN];
__device__ float  g_dist[BB][NN];
__device__ float  g_dpart[BB][RCTAS];
__device__ float  g_mpart[BB][8][16];

__device__ __forceinline__ float frcp(float x) {
    float r; asm("rcp.approx.f32 %0, %1;" : "=f"(r) : "f"(x)); return r;
}
__device__ __forceinline__ float fex2(float x) {
    float r; asm("ex2.approx.f32 %0, %1;" : "=f"(r) : "f"(x)); return r;
}
__device__ __forceinline__ int clampi(int v, int lo, int hi) {
    return v < lo ? lo : (v > hi ? hi : v);
}

// ---------------------------------------------------------------------------
// Kernel 1: per-batch grid build (bbox, histogram, scan, scatter). 1 CTA/batch.
// ---------------------------------------------------------------------------
__global__ void __launch_bounds__(512)
cpnet_bin(const float* __restrict__ pc2) {
    const int b = blockIdx.x;
    const float* p2 = pc2 + (size_t)b * 4 * NN;
    const int tid = threadIdx.x;
    const int lane = tid & 31;
    const int w = tid >> 5;  // 16 warps

    __shared__ unsigned cnt[NCELL];
    __shared__ unsigned sstart[NCELL];
    __shared__ float red[16 * 6];
    __shared__ float gp[8];
    __shared__ unsigned wsum[16], woff[16];

    // ---- bbox ----
    float mnx = FLT_MAX, mny = FLT_MAX, mnz = FLT_MAX;
    float mxx = -FLT_MAX, mxy = -FLT_MAX, mxz = -FLT_MAX;
    for (int k = 0; k < NN / 512; ++k) {
        int i = k * 512 + tid;
        float x = p2[i], y = p2[NN + i], z = p2[2 * NN + i];
        mnx = fminf(mnx, x); mxx = fmaxf(mxx, x);
        mny = fminf(mny, y); mxy = fmaxf(mxy, y);
        mnz = fminf(mnz, z); mxz = fmaxf(mxz, z);
    }
    #pragma unroll
    for (int o = 16; o; o >>= 1) {
        mnx = fminf(mnx, __shfl_xor_sync(~0u, mnx, o));
        mny = fminf(mny, __shfl_xor_sync(~0u, mny, o));
        mnz = fminf(mnz, __shfl_xor_sync(~0u, mnz, o));
        mxx = fmaxf(mxx, __shfl_xor_sync(~0u, mxx, o));
        mxy = fmaxf(mxy, __shfl_xor_sync(~0u, mxy, o));
        mxz = fmaxf(mxz, __shfl_xor_sync(~0u, mxz, o));
    }
    if (lane == 0) {
        red[w] = mnx; red[16 + w] = mny; red[32 + w] = mnz;
        red[48 + w] = mxx; red[64 + w] = mxy; red[80 + w] = mxz;
    }
    __syncthreads();
    if (tid == 0) {
        float a0 = red[0], a1 = red[16], a2 = red[32];
        float b0 = red[48], b1 = red[64], b2 = red[80];
        for (int i = 1; i < 16; ++i) {
            a0 = fminf(a0, red[i]);      a1 = fminf(a1, red[16 + i]);
            a2 = fminf(a2, red[32 + i]); b0 = fmaxf(b0, red[48 + i]);
            b1 = fmaxf(b1, red[64 + i]); b2 = fmaxf(b2, red[80 + i]);
        }
        float wx = fmaxf(b0 - a0, 1e-6f);
        float wy = fmaxf(b1 - a1, 1e-6f);
        float wz = fmaxf(b2 - a2, 1e-6f);
        gp[0] = a0; gp[1] = a1; gp[2] = a2;
        gp[3] = (float)GC / wx; gp[4] = (float)GC / wy; gp[5] = (float)GC / wz;
        gp[6] = fminf(wx / GC, fminf(wy / GC, wz / GC));
        for (int i = 0; i < 7; ++i) g_grid[b][i] = gp[i];
    }
    __syncthreads();
    const float mbx = gp[0], mby = gp[1], mbz = gp[2];
    const float icwx = gp[3], icwy = gp[4], icwz = gp[5];

    // ---- histogram ----
    for (int k = 0; k < NCELL / 512; ++k) cnt[k * 512 + tid] = 0;
    __syncthreads();
    for (int k = 0; k < NN / 512; ++k) {
        int i = k * 512 + tid;
        float x = p2[i], y = p2[NN + i], z = p2[2 * NN + i];
        int cx = clampi((int)floorf((x - mbx) * icwx), 0, GC - 1);
        int cy = clampi((int)floorf((y - mby) * icwy), 0, GC - 1);
        int cz = clampi((int)floorf((z - mbz) * icwz), 0, GC - 1);
        atomicAdd(&cnt[cx + GC * (cy + GC * cz)], 1u);
    }
    __syncthreads();

    // ---- exclusive scan (8 cells/thread) ----
    unsigned v[8], tot = 0;
    #pragma unroll
    for (int j = 0; j < 8; ++j) { v[j] = cnt[tid * 8 + j]; tot += v[j]; }
    unsigned x = tot;
    #pragma unroll
    for (int o = 1; o < 32; o <<= 1) {
        unsigned t = __shfl_up_sync(~0u, x, o);
        if (lane >= o) x += t;
    }
    if (lane == 31) wsum[w] = x;
    __syncthreads();
    if (tid < 16) {
        unsigned y = wsum[tid];
        #pragma unroll
        for (int o = 1; o < 16; o <<= 1) {
            unsigned t = __shfl_up_sync(0xffffu, y, o);
            if (tid >= o) y += t;
        }
        woff[tid] = y - wsum[tid];
    }
    __syncthreads();
    unsigned run = (x - tot) + woff[w];
    #pragma unroll
    for (int j = 0; j < 8; ++j) {
        sstart[tid * 8 + j] = run;
        g_cellstart[b][tid * 8 + j] = (int)run;
        run += v[j];
    }
    if (tid == 511) g_cellstart[b][NCELL] = NN;
    __syncthreads();

    // ---- scatter (reuse cnt as cursor) ----
    for (int k = 0; k < NCELL / 512; ++k) cnt[k * 512 + tid] = 0;
    __syncthreads();
    for (int k = 0; k < NN / 512; ++k) {
        int i = k * 512 + tid;
        float xx = p2[i], yy = p2[NN + i], zz = p2[2 * NN + i];
        int cx = clampi((int)floorf((xx - mbx) * icwx), 0, GC - 1);
        int cy = clampi((int)floorf((yy - mby) * icwy), 0, GC - 1);
        int cz = clampi((int)floorf((zz - mbz) * icwz), 0, GC - 1);
        int cid = cx + GC * (cy + GC * cz);
        unsigned off = atomicAdd(&cnt[cid], 1u);
        g_spts[b][sstart[cid] + off] = make_float4(xx, yy, zz, 0.f);
    }
}

// ---------------------------------------------------------------------------
// Kernel 2: rows — one warp per row. Exact NN via grid, sparse accumulation
// over threshold sphere; dense fallback (identical math) for wide-softmax rows.
// ---------------------------------------------------------------------------
__global__ void __launch_bounds__(256)
cpnet_rows(const float* __restrict__ pc1, const float* __restrict__ pc2) {
    const int b = blockIdx.y;
    const int wid = threadIdx.x >> 5, lane = threadIdx.x & 31;
    const int n = blockIdx.x * RPC + wid;
    const float* p1 = pc1 + (size_t)b * 4 * NN;
    const float* p2 = pc2 + (size_t)b * 4 * NN;
    const float4* sp = g_spts[b];
    const int* cs = g_cellstart[b];

    const float mbx = g_grid[b][0], mby = g_grid[b][1], mbz = g_grid[b][2];
    const float icwx = g_grid[b][3], icwy = g_grid[b][4], icwz = g_grid[b][5];
    const float minw = g_grid[b][6];

    const float px = p1[n], py = p1[NN + n], pz = p1[2 * NN + n];
    const int qx = clampi((int)floorf((px - mbx) * icwx), 0, GC - 1);
    const int qy = clampi((int)floorf((py - mby) * icwy), 0, GC - 1);
    const int qz = clampi((int)floorf((pz - mbz) * icwz), 0, GC - 1);

    // ---- exact NN: 27-box, then 5^3 shell; else dense ----
    float dmin = FLT_MAX;
    if (lane < 27) {
        int cx = qx + lane % 3 - 1, cy = qy + (lane / 3) % 3 - 1, cz = qz + lane / 9 - 1;
        if ((unsigned)cx < GC && (unsigned)cy < GC && (unsigned)cz < GC) {
            int cid = cx + GC * (cy + GC * cz);
            for (int i = cs[cid]; i < cs[cid + 1]; ++i) {
                float4 q = sp[i];
                float dx = px - q.x, dy = py - q.y, dz = pz - q.z;
                dmin = fminf(dmin, fmaf(dx, dx, fmaf(dy, dy, dz * dz)));
            }
        }
    }
    #pragma unroll
    for (int o = 16; o; o >>= 1) dmin = fminf(dmin, __shfl_xor_sync(~0u, dmin, o));
    bool have = dmin < minw * minw;  // ring-2 points are >= minw away
    if (!have) {
        for (int j = lane; j < 125; j += 32) {
            int d5x = j % 5 - 2, d5y = (j / 5) % 5 - 2, d5z = j / 25 - 2;
            if (d5x > -2 && d5x < 2 && d5y > -2 && d5y < 2 && d5z > -2 && d5z < 2)
                continue;  // inner 27 already scanned
            int cx = qx + d5x, cy = qy + d5y, cz = qz + d5z;
            if ((unsigned)cx < GC && (unsigned)cy < GC && (unsigned)cz < GC) {
                int cid = cx + GC * (cy + GC * cz);
                for (int i = cs[cid]; i < cs[cid + 1]; ++i) {
                    float4 q = sp[i];
                    float dx = px - q.x, dy = py - q.y, dz = pz - q.z;
                    dmin = fminf(dmin, fmaf(dx, dx, fmaf(dy, dy, dz * dz)));
                }
            }
        }
        #pragma unroll
        for (int o = 16; o; o >>= 1) dmin = fminf(dmin, __shfl_xor_sync(~0u, dmin, o));
        have = dmin < 4.f * minw * minw;  // ring-3 points are >= 2*minw away
    }

    float c = 0.f;
    bool dense = !have;
    if (have) {
        c = kF2 * frcp(fmaxf(dmin, kEPS));
        if (c <= 36.f) dense = true;  // wide softmax: everything contributes
    }

    float Z = 0.f, ax = 0.f, ay = 0.f, az = 0.f;
    if (!dense) {
        float dthr = kF2 * frcp(c - 35.f);  // weight >= 2^-35 inside this d
        float rthr = sqrtf(dthr);
        int lox = clampi((int)floorf((px - rthr - mbx) * icwx), 0, GC - 1);
        int hix = clampi((int)floorf((px + rthr - mbx) * icwx), 0, GC - 1);
        int loy = clampi((int)floorf((py - rthr - mby) * icwy), 0, GC - 1);
        int hiy = clampi((int)floorf((py + rthr - mby) * icwy), 0, GC - 1);
        int loz = clampi((int)floorf((pz - rthr - mbz) * icwz), 0, GC - 1);
        int hiz = clampi((int)floorf((pz + rthr - mbz) * icwz), 0, GC - 1);
        int bx = hix - lox + 1, by = hiy - loy + 1, bz = hiz - loz + 1;
        if (bx > 3 || by > 3 || bz > 3) {
            dense = true;
        } else {
            int nc = bx * by * bz;  // <= 27
            if (lane < nc) {
                int cx = lox + lane % bx;
                int t = lane / bx;
                int cy = loy + t % by, cz = loz + t / by;
                int cid = cx + GC * (cy + GC * cz);
                for (int i = cs[cid]; i < cs[cid + 1]; ++i) {
                    float4 q = sp[i];
                    float dx = px - q.x, dy = py - q.y, dz = pz - q.z;
                    float d = fmaf(dx, dx, fmaf(dy, dy, dz * dz));
                    float ww = fex2(fmaf(frcp(fmaxf(d, kEPS)), kF2, -c));
                    Z += ww;
                    ax = fmaf(ww, q.x, ax);
                    ay = fmaf(ww, q.y, ay);
                    az = fmaf(ww, q.z, az);
                }
            }
        }
    }
    if (dense) {
        if (!have) {  // exact min over everything
            dmin = FLT_MAX;
            for (int m = lane; m < NN; m += 32) {
                float dx = px - p2[m], dy = py - p2[NN + m], dz = pz - p2[2 * NN + m];
                dmin = fminf(dmin, fmaf(dx, dx, fmaf(dy, dy, dz * dz)));
            }
            #pragma unroll
            for (int o = 16; o; o >>= 1) dmin = fminf(dmin, __shfl_xor_sync(~0u, dmin, o));
            c = kF2 * frcp(fmaxf(dmin, kEPS));
        }
        Z = 0.f; ax = 0.f; ay = 0.f; az = 0.f;
        for (int m = lane; m < NN; m += 32) {
            float x2 = p2[m], y2 = p2[NN + m], z2 = p2[2 * NN + m];
            float dx = px - x2, dy = py - y2, dz = pz - z2;
            float d = fmaf(dx, dx, fmaf(dy, dy, dz * dz));
            float ww = fex2(fmaf(frcp(fmaxf(d, kEPS)), kF2, -c));
            Z += ww;
            ax = fmaf(ww, x2, ax);
            ay = fmaf(ww, y2, ay);
            az = fmaf(ww, z2, az);
        }
    }

    #pragma unroll
    for (int o = 16; o; o >>= 1) {
        Z  += __shfl_xor_sync(~0u, Z,  o);
        ax += __shfl_xor_sync(~0u, ax, o);
        ay += __shfl_xor_sync(~0u, ay, o);
        az += __shfl_xor_sync(~0u, az, o);
    }

    __shared__ float sds[RPC];
    if (lane == 0) {
        float rz = 1.0f / Z;
        float q0 = ax * rz, q1 = ay * rz, q2 = az * rz;
        float dx = px - q0, dy = py - q1, dz = pz - q2;
        float dist = sqrtf(dx * dx + dy * dy + dz * dz);
        g_pcn[b][0][n] = q0; g_pcn[b][1][n] = q1; g_pcn[b][2][n] = q2;
        g_dist[b][n] = dist;
        sds[wid] = dist;
    }
    __syncthreads();
    if (threadIdx.x == 0) {
        float s = 0.f;
        #pragma unroll
        for (int i = 0; i < RPC; ++i) s += sds[i];
        g_dpart[b][blockIdx.x] = s;
    }
}

// ---------------------------------------------------------------------------
// Kernel 3: moments per slice (mean from g_dpart partials).
// ---------------------------------------------------------------------------
__global__ void __launch_bounds__(256)
cpnet_moments(const float* __restrict__ pc1) {
    const int b = blockIdx.y;
    const int slice = blockIdx.x;
    const float* p1 = pc1 + (size_t)b * 4 * NN;
    const int tid = threadIdx.x;
    const int lane = tid & 31;
    const int w = tid >> 5;

    __shared__ float smW[8];
    __shared__ float smP[8][16];

    float v = g_dpart[b][tid] + g_dpart[b][tid + 256];
    #pragma unroll
    for (int o = 16; o; o >>= 1) v += __shfl_xor_sync(~0u, v, o);
    if (lane == 0) smW[w] = v;
    __syncthreads();
    double ms = 0.0;
    #pragma unroll
    for (int i = 0; i < 8; ++i) ms += (double)smW[i];
    const float mean = (float)(ms * (1.0 / (double)NN));

    float P[16];
    #pragma unroll
    for (int i = 0; i < 16; ++i) P[i] = 0.f;
    #pragma unroll
    for (int k = 0; k < 2; ++k) {
        int n = slice * 512 + k * 256 + tid;
        float dist = g_dist[b][n];
        float z = (dist - mean - kEPS) * 1e10f;
        float ind = 1.0f / (1.0f + __expf(z));
        float axx = p1[n], ayy = p1[NN + n], azz = p1[2 * NN + n];
        float bx = g_pcn[b][0][n], by = g_pcn[b][1][n], bz = g_pcn[b][2][n];
        float iax = ind * axx, iay = ind * ayy, iaz = ind * azz;
        P[0] += ind;
        P[1] += iax; P[2] += iay; P[3] += iaz;
        P[4] += ind * bx; P[5] += ind * by; P[6] += ind * bz;
        P[7]  += iax * bx; P[8]  += iax * by; P[9]  += iax * bz;
        P[10] += iay * bx; P[11] += iay * by; P[12] += iay * bz;
        P[13] += iaz * bx; P[14] += iaz * by; P[15] += iaz * bz;
    }
    #pragma unroll
    for (int o = 16; o; o >>= 1)
        #pragma unroll
        for (int i = 0; i < 16; ++i)
            P[i] += __shfl_xor_sync(~0u, P[i], o);
    if (lane == 0) {
        #pragma unroll
        for (int i = 0; i < 16; ++i) smP[w][i] = P[i];
    }
    __syncthreads();
    if (w == 0 && lane < 16) {
        float s = 0.f;
        #pragma unroll
        for (int ww = 0; ww < 8; ++ww) s += smP[ww][lane];
        g_mpart[b][slice][lane] = s;
    }
}

// ---------------------------------------------------------------------------
// Kernel 4: SVD tail per batch.
// ---------------------------------------------------------------------------
__global__ void cpnet_svd(float* __restrict__ out) {
    const int b = blockIdx.x;
    if (threadIdx.x != 0) return;

    double S[16];
    #pragma unroll
    for (int i = 0; i < 16; ++i) {
        double s = 0.0;
        #pragma unroll
        for (int sl = 0; sl < 8; ++sl) s += (double)g_mpart[b][sl][i];
        S[i] = s;
    }

    const double sw = S[0];
    const double inv_sw = 1.0 / sw;
    float c1v[3] = {(float)(S[1] * inv_sw), (float)(S[2] * inv_sw), (float)(S[3] * inv_sw)};
    float c2v[3] = {(float)(S[4] * inv_sw), (float)(S[5] * inv_sw), (float)(S[6] * inv_sw)};
    float H[3][3];
    #pragma unroll
    for (int i = 0; i < 3; ++i)
        #pragma unroll
        for (int j = 0; j < 3; ++j)
            H[i][j] = (float)(S[7 + i * 3 + j] - S[1 + i] * S[4 + j] * inv_sw);

    float G[3][3];
    #pragma unroll
    for (int i = 0; i < 3; ++i)
        #pragma unroll
        for (int j = 0; j < 3; ++j)
            G[i][j] = H[0][i] * H[0][j] + H[1][i] * H[1][j] + H[2][i] * H[2][j];
    float V[3][3] = {{1, 0, 0}, {0, 1, 0}, {0, 0, 1}};
    const int PP[3] = {0, 0, 1}, QQ[3] = {1, 2, 2};
    #pragma unroll
    for (int it = 0; it < 18; ++it) {
        int p = PP[it % 3], q = QQ[it % 3];
        float apq = G[p][q];
        if (fabsf(apq) > 1e-25f) {
            float theta = (G[q][q] - G[p][p]) / (2.0f * apq);
            float t = copysignf(1.0f, theta) / (fabsf(theta) + sqrtf(theta * theta + 1.0f));
            float c = rsqrtf(t * t + 1.0f);
            float sn = t * c;
            #pragma unroll
            for (int k = 0; k < 3; ++k) {
                float gkp = G[k][p], gkq = G[k][q];
                G[k][p] = c * gkp - sn * gkq;
                G[k][q] = sn * gkp + c * gkq;
            }
            #pragma unroll
            for (int k = 0; k < 3; ++k) {
                float gpk = G[p][k], gqk = G[q][k];
                G[p][k] = c * gpk - sn * gqk;
                G[q][k] = sn * gpk + c * gqk;
            }
            #pragma unroll
            for (int k = 0; k < 3; ++k) {
                float vkp = V[k][p], vkq = V[k][q];
                V[k][p] = c * vkp - sn * vkq;
                V[k][q] = sn * vkp + c * vkq;
            }
        }
    }
    float ev[3] = {G[0][0], G[1][1], G[2][2]};
    #pragma unroll
    for (int a = 0; a < 2; ++a)
        #pragma unroll
        for (int bc = 1; bc < 3; ++bc)
            if (bc > a && ev[bc] > ev[a]) {
                float te = ev[a]; ev[a] = ev[bc]; ev[bc] = te;
                #pragma unroll
                for (int k = 0; k < 3; ++k) {
                    float tv = V[k][a]; V[k][a] = V[k][bc]; V[k][bc] = tv;
                }
            }
    float U[3][3];
    #pragma unroll
    for (int j = 0; j < 3; ++j) {
        float sig = sqrtf(fmaxf(ev[j], 0.f));
        float inv = (sig > 1e-20f) ? (1.0f / sig) : 0.f;
        #pragma unroll
        for (int i = 0; i < 3; ++i)
            U[i][j] = (H[i][0] * V[0][j] + H[i][1] * V[1][j] + H[i][2] * V[2][j]) * inv;
    }
    auto det3 = [](float M[3][3]) {
        return M[0][0] * (M[1][1] * M[2][2] - M[1][2] * M[2][1])
             - M[0][1] * (M[1][0] * M[2][2] - M[1][2] * M[2][0])
             + M[0][2] * (M[1][0] * M[2][1] - M[1][1] * M[2][0]);
    };
    float sign = (det3(U) * det3(V) < 0.f) ? -1.f : 1.f;
    V[0][2] *= sign; V[1][2] *= sign; V[2][2] *= sign;
    float R[3][3];
    #pragma unroll
    for (int i = 0; i < 3; ++i)
        #pragma unroll
        for (int j = 0; j < 3; ++j)
            R[i][j] = V[i][0] * U[j][0] + V[i][1] * U[j][1] + V[i][2] * U[j][2];
    float tt[3];
    #pragma unroll
    for (int i = 0; i < 3; ++i)
        tt[i] = c2v[i] - (R[i][0] * c1v[0] + R[i][1] * c1v[1] + R[i][2] * c1v[2]);

    float* T = out + b * 16;
    #pragma unroll
    for (int i = 0; i < 3; ++i) {
        T[i * 4 + 0] = R[i][0];
        T[i * 4 + 1] = R[i][1];
        T[i * 4 + 2] = R[i][2];
        T[i * 4 + 3] = tt[i];
    }
    T[12] = 0.f; T[13] = 0.f; T[14] = 0.f; T[15] = 1.f;

    auto sgn = [](float x) { return x >= 0.f ? 1.f : -1.f; };
    float qw = 0.5f * sqrtf(fmaxf(1.f + R[0][0] + R[1][1] + R[2][2], 1e-12f));
    float qx = 0.5f * sqrtf(fmaxf(1.f + R[0][0] - R[1][1] - R[2][2], 1e-12f)) * sgn(R[2][1] - R[1][2]);
    float qy = 0.5f * sqrtf(fmaxf(1.f - R[0][0] + R[1][1] - R[2][2], 1e-12f)) * sgn(R[0][2] - R[2][0]);
    float qz = 0.5f * sqrtf(fmaxf(1.f - R[0][0] - R[1][1] + R[2][2], 1e-12f)) * sgn(R[1][0] - R[0][1]);
    float* qo = out + BB * 16 + b * 4;
    qo[0] = qw; qo[1] = qx; qo[2] = qy; qo[3] = qz;
    float* to = out + BB * 16 + BB * 4 + b * 3;
    to[0] = tt[0]; to[1] = tt[1]; to[2] = tt[2];
}

// ---------------------------------------------------------------------------
extern "C" void kernel_launch(void* const* d_in, const int* in_sizes, int n_in,
                              void* d_out, int out_size) {
    const float* pc1 = (const float*)d_in[0];
    const float* pc2 = (const float*)d_in[1];
    float* out = (float*)d_out;

    cpnet_bin<<<BB, 512>>>(pc2);
    dim3 rgrid(RCTAS, BB);   // 512 x 8 CTAs, 8 warps = 8 rows each
    cpnet_rows<<<rgrid, 256>>>(pc1, pc2);
    dim3 mgrid(8, BB);
    cpnet_moments<<<mgrid, 256>>>(pc1);
    cpnet_svd<<<BB, 32>>>(out);
}

// round 10
// speedup vs baseline: 1.6154x; 1.0976x over previous
#include <cuda_runtime.h>
#include <math.h>
#include <float.h>

#define BB 8
#define NN 4096
#define GC 16                 // grid cells per axis
#define NCELL (GC * GC * GC)  // 4096
#define RPC 8                 // rows per CTA (1 row per warp)
#define RCTAS (NN / RPC)      // 512 row-CTAs per batch

static __device__ __constant__ float kEPS = 1e-5f;
static __device__ __constant__ float kF2  = 2.8853900817779268f; // FACT*log2(e)

// Scratch (device globals; fully overwritten every run)
__device__ float4 g_spts[BB][NN];             // cell-sorted pc2 points
__device__ int    g_cellstart[BB][NCELL + 1];
__device__ float  g_grid[BB][8];              // mbx,mby,mbz,icwx,icwy,icwz,minw
__device__ float  g_pcn[BB][3][NN];
__device__ float  g_dist[BB][NN];
__device__ float  g_dpart[BB][RCTAS];
__device__ float  g_mpart[BB][8][16];

__device__ __forceinline__ float frcp(float x) {
    float r; asm("rcp.approx.f32 %0, %1;" : "=f"(r) : "f"(x)); return r;
}
__device__ __forceinline__ float fex2(float x) {
    float r; asm("ex2.approx.f32 %0, %1;" : "=f"(r) : "f"(x)); return r;
}
__device__ __forceinline__ int clampi(int v, int lo, int hi) {
    return v < lo ? lo : (v > hi ? hi : v);
}

// ---------------------------------------------------------------------------
// Kernel 1: per-batch grid build (bbox, histogram, scan, scatter). 1 CTA/batch.
// ---------------------------------------------------------------------------
__global__ void __launch_bounds__(512)
cpnet_bin(const float* __restrict__ pc2) {
    const int b = blockIdx.x;
    const float* p2 = pc2 + (size_t)b * 4 * NN;
    const int tid = threadIdx.x;
    const int lane = tid & 31;
    const int w = tid >> 5;  // 16 warps

    __shared__ unsigned cnt[NCELL];
    __shared__ unsigned sstart[NCELL];
    __shared__ float red[16 * 6];
    __shared__ float gp[8];
    __shared__ unsigned wsum[16], woff[16];

    // ---- bbox ----
    float mnx = FLT_MAX, mny = FLT_MAX, mnz = FLT_MAX;
    float mxx = -FLT_MAX, mxy = -FLT_MAX, mxz = -FLT_MAX;
    for (int k = 0; k < NN / 512; ++k) {
        int i = k * 512 + tid;
        float x = p2[i], y = p2[NN + i], z = p2[2 * NN + i];
        mnx = fminf(mnx, x); mxx = fmaxf(mxx, x);
        mny = fminf(mny, y); mxy = fmaxf(mxy, y);
        mnz = fminf(mnz, z); mxz = fmaxf(mxz, z);
    }
    #pragma unroll
    for (int o = 16; o; o >>= 1) {
        mnx = fminf(mnx, __shfl_xor_sync(~0u, mnx, o));
        mny = fminf(mny, __shfl_xor_sync(~0u, mny, o));
        mnz = fminf(mnz, __shfl_xor_sync(~0u, mnz, o));
        mxx = fmaxf(mxx, __shfl_xor_sync(~0u, mxx, o));
        mxy = fmaxf(mxy, __shfl_xor_sync(~0u, mxy, o));
        mxz = fmaxf(mxz, __shfl_xor_sync(~0u, mxz, o));
    }
    if (lane == 0) {
        red[w] = mnx; red[16 + w] = mny; red[32 + w] = mnz;
        red[48 + w] = mxx; red[64 + w] = mxy; red[80 + w] = mxz;
    }
    __syncthreads();
    if (tid == 0) {
        float a0 = red[0], a1 = red[16], a2 = red[32];
        float b0 = red[48], b1 = red[64], b2 = red[80];
        for (int i = 1; i < 16; ++i) {
            a0 = fminf(a0, red[i]);      a1 = fminf(a1, red[16 + i]);
            a2 = fminf(a2, red[32 + i]); b0 = fmaxf(b0, red[48 + i]);
            b1 = fmaxf(b1, red[64 + i]); b2 = fmaxf(b2, red[80 + i]);
        }
        float wx = fmaxf(b0 - a0, 1e-6f);
        float wy = fmaxf(b1 - a1, 1e-6f);
        float wz = fmaxf(b2 - a2, 1e-6f);
        gp[0] = a0; gp[1] = a1; gp[2] = a2;
        gp[3] = (float)GC / wx; gp[4] = (float)GC / wy; gp[5] = (float)GC / wz;
        gp[6] = fminf(wx / GC, fminf(wy / GC, wz / GC));
        for (int i = 0; i < 7; ++i) g_grid[b][i] = gp[i];
    }
    __syncthreads();
    const float mbx = gp[0], mby = gp[1], mbz = gp[2];
    const float icwx = gp[3], icwy = gp[4], icwz = gp[5];

    // ---- histogram ----
    for (int k = 0; k < NCELL / 512; ++k) cnt[k * 512 + tid] = 0;
    __syncthreads();
    for (int k = 0; k < NN / 512; ++k) {
        int i = k * 512 + tid;
        float x = p2[i], y = p2[NN + i], z = p2[2 * NN + i];
        int cx = clampi((int)floorf((x - mbx) * icwx), 0, GC - 1);
        int cy = clampi((int)floorf((y - mby) * icwy), 0, GC - 1);
        int cz = clampi((int)floorf((z - mbz) * icwz), 0, GC - 1);
        atomicAdd(&cnt[cx + GC * (cy + GC * cz)], 1u);
    }
    __syncthreads();

    // ---- exclusive scan (8 cells/thread) ----
    unsigned v[8], tot = 0;
    #pragma unroll
    for (int j = 0; j < 8; ++j) { v[j] = cnt[tid * 8 + j]; tot += v[j]; }
    unsigned x = tot;
    #pragma unroll
    for (int o = 1; o < 32; o <<= 1) {
        unsigned t = __shfl_up_sync(~0u, x, o);
        if (lane >= o) x += t;
    }
    if (lane == 31) wsum[w] = x;
    __syncthreads();
    if (tid < 16) {
        unsigned y = wsum[tid];
        #pragma unroll
        for (int o = 1; o < 16; o <<= 1) {
            unsigned t = __shfl_up_sync(0xffffu, y, o);
            if (tid >= o) y += t;
        }
        woff[tid] = y - wsum[tid];
    }
    __syncthreads();
    unsigned run = (x - tot) + woff[w];
    #pragma unroll
    for (int j = 0; j < 8; ++j) {
        sstart[tid * 8 + j] = run;
        g_cellstart[b][tid * 8 + j] = (int)run;
        run += v[j];
    }
    if (tid == 511) g_cellstart[b][NCELL] = NN;
    __syncthreads();

    // ---- scatter (reuse cnt as cursor) ----
    for (int k = 0; k < NCELL / 512; ++k) cnt[k * 512 + tid] = 0;
    __syncthreads();
    for (int k = 0; k < NN / 512; ++k) {
        int i = k * 512 + tid;
        float xx = p2[i], yy = p2[NN + i], zz = p2[2 * NN + i];
        int cx = clampi((int)floorf((xx - mbx) * icwx), 0, GC - 1);
        int cy = clampi((int)floorf((yy - mby) * icwy), 0, GC - 1);
        int cz = clampi((int)floorf((zz - mbz) * icwz), 0, GC - 1);
        int cid = cx + GC * (cy + GC * cz);
        unsigned off = atomicAdd(&cnt[cid], 1u);
        g_spts[b][sstart[cid] + off] = make_float4(xx, yy, zz, 0.f);
    }
}

// ---------------------------------------------------------------------------
// Kernel 2: rows — one warp per row. Exact NN via grid, sparse accumulation
// over threshold sphere; dense fallback (identical math) for wide-softmax rows.
// ---------------------------------------------------------------------------
__global__ void __launch_bounds__(256)
cpnet_rows(const float* __restrict__ pc1, const float* __restrict__ pc2) {
    const int b = blockIdx.y;
    const int wid = threadIdx.x >> 5, lane = threadIdx.x & 31;
    const int n = blockIdx.x * RPC + wid;
    const float* p1 = pc1 + (size_t)b * 4 * NN;
    const float* p2 = pc2 + (size_t)b * 4 * NN;
    const float4* sp = g_spts[b];
    const int* cs = g_cellstart[b];

    const float mbx = g_grid[b][0], mby = g_grid[b][1], mbz = g_grid[b][2];
    const float icwx = g_grid[b][3], icwy = g_grid[b][4], icwz = g_grid[b][5];
    const float minw = g_grid[b][6];

    const float px = p1[n], py = p1[NN + n], pz = p1[2 * NN + n];
    const int qx = clampi((int)floorf((px - mbx) * icwx), 0, GC - 1);
    const int qy = clampi((int)floorf((py - mby) * icwy), 0, GC - 1);
    const int qz = clampi((int)floorf((pz - mbz) * icwz), 0, GC - 1);

    // ---- exact NN: 27-box, then 5^3 shell; else dense ----
    float dmin = FLT_MAX;
    if (lane < 27) {
        int cx = qx + lane % 3 - 1, cy = qy + (lane / 3) % 3 - 1, cz = qz + lane / 9 - 1;
        if ((unsigned)cx < GC && (unsigned)cy < GC && (unsigned)cz < GC) {
            int cid = cx + GC * (cy + GC * cz);
            for (int i = cs[cid]; i < cs[cid + 1]; ++i) {
                float4 q = sp[i];
                float dx = px - q.x, dy = py - q.y, dz = pz - q.z;
                dmin = fminf(dmin, fmaf(dx, dx, fmaf(dy, dy, dz * dz)));
            }
        }
    }
    #pragma unroll
    for (int o = 16; o; o >>= 1) dmin = fminf(dmin, __shfl_xor_sync(~0u, dmin, o));
    bool have = dmin < minw * minw;  // ring-2 points are >= minw away
    if (!have) {
        for (int j = lane; j < 125; j += 32) {
            int d5x = j % 5 - 2, d5y = (j / 5) % 5 - 2, d5z = j / 25 - 2;
            if (d5x > -2 && d5x < 2 && d5y > -2 && d5y < 2 && d5z > -2 && d5z < 2)
                continue;  // inner 27 already scanned
            int cx = qx + d5x, cy = qy + d5y, cz = qz + d5z;
            if ((unsigned)cx < GC && (unsigned)cy < GC && (unsigned)cz < GC) {
                int cid = cx + GC * (cy + GC * cz);
                for (int i = cs[cid]; i < cs[cid + 1]; ++i) {
                    float4 q = sp[i];
                    float dx = px - q.x, dy = py - q.y, dz = pz - q.z;
                    dmin = fminf(dmin, fmaf(dx, dx, fmaf(dy, dy, dz * dz)));
                }
            }
        }
        #pragma unroll
        for (int o = 16; o; o >>= 1) dmin = fminf(dmin, __shfl_xor_sync(~0u, dmin, o));
        have = dmin < 4.f * minw * minw;  // ring-3 points are >= 2*minw away
    }

    float c = 0.f;
    bool dense = !have;
    if (have) {
        c = kF2 * frcp(fmaxf(dmin, kEPS));
        if (c <= 36.f) dense = true;  // wide softmax: everything contributes
    }

    float Z = 0.f, ax = 0.f, ay = 0.f, az = 0.f;
    if (!dense) {
        float dthr = kF2 * frcp(c - 35.f);  // weight >= 2^-35 inside this d
        float rthr = sqrtf(dthr);
        int lox = clampi((int)floorf((px - rthr - mbx) * icwx), 0, GC - 1);
        int hix = clampi((int)floorf((px + rthr - mbx) * icwx), 0, GC - 1);
        int loy = clampi((int)floorf((py - rthr - mby) * icwy), 0, GC - 1);
        int hiy = clampi((int)floorf((py + rthr - mby) * icwy), 0, GC - 1);
        int loz = clampi((int)floorf((pz - rthr - mbz) * icwz), 0, GC - 1);
        int hiz = clampi((int)floorf((pz + rthr - mbz) * icwz), 0, GC - 1);
        int bx = hix - lox + 1, by = hiy - loy + 1, bz = hiz - loz + 1;
        if (bx > 3 || by > 3 || bz > 3) {
            dense = true;
        } else {
            int nc = bx * by * bz;  // <= 27
            if (lane < nc) {
                int cx = lox + lane % bx;
                int t = lane / bx;
                int cy = loy + t % by, cz = loz + t / by;
                int cid = cx + GC * (cy + GC * cz);
                for (int i = cs[cid]; i < cs[cid + 1]; ++i) {
                    float4 q = sp[i];
                    float dx = px - q.x, dy = py - q.y, dz = pz - q.z;
                    float d = fmaf(dx, dx, fmaf(dy, dy, dz * dz));
                    float ww = fex2(fmaf(frcp(fmaxf(d, kEPS)), kF2, -c));
                    Z += ww;
                    ax = fmaf(ww, q.x, ax);
                    ay = fmaf(ww, q.y, ay);
                    az = fmaf(ww, q.z, az);
                }
            }
        }
    }
    if (dense) {
        if (!have) {  // exact min over everything
            dmin = FLT_MAX;
            for (int m = lane; m < NN; m += 32) {
                float dx = px - p2[m], dy = py - p2[NN + m], dz = pz - p2[2 * NN + m];
                dmin = fminf(dmin, fmaf(dx, dx, fmaf(dy, dy, dz * dz)));
            }
            #pragma unroll
            for (int o = 16; o; o >>= 1) dmin = fminf(dmin, __shfl_xor_sync(~0u, dmin, o));
            c = kF2 * frcp(fmaxf(dmin, kEPS));
        }
        Z = 0.f; ax = 0.f; ay = 0.f; az = 0.f;
        for (int m = lane; m < NN; m += 32) {
            float x2 = p2[m], y2 = p2[NN + m], z2 = p2[2 * NN + m];
            float dx = px - x2, dy = py - y2, dz = pz - z2;
            float d = fmaf(dx, dx, fmaf(dy, dy, dz * dz));
            float ww = fex2(fmaf(frcp(fmaxf(d, kEPS)), kF2, -c));
            Z += ww;
            ax = fmaf(ww, x2, ax);
            ay = fmaf(ww, y2, ay);
            az = fmaf(ww, z2, az);
        }
    }

    #pragma unroll
    for (int o = 16; o; o >>= 1) {
        Z  += __shfl_xor_sync(~0u, Z,  o);
        ax += __shfl_xor_sync(~0u, ax, o);
        ay += __shfl_xor_sync(~0u, ay, o);
        az += __shfl_xor_sync(~0u, az, o);
    }

    __shared__ float sds[RPC];
    if (lane == 0) {
        float rz = 1.0f / Z;
        float q0 = ax * rz, q1 = ay * rz, q2 = az * rz;
        float dx = px - q0, dy = py - q1, dz = pz - q2;
        float dist = sqrtf(dx * dx + dy * dy + dz * dz);
        g_pcn[b][0][n] = q0; g_pcn[b][1][n] = q1; g_pcn[b][2][n] = q2;
        g_dist[b][n] = dist;
        sds[wid] = dist;
    }
    __syncthreads();
    if (threadIdx.x == 0) {
        float s = 0.f;
        #pragma unroll
        for (int i = 0; i < RPC; ++i) s += sds[i];
        g_dpart[b][blockIdx.x] = s;
    }
}

// ---------------------------------------------------------------------------
// Kernel 3: moments per slice (mean from g_dpart partials).
// ---------------------------------------------------------------------------
__global__ void __launch_bounds__(256)
cpnet_moments(const float* __restrict__ pc1) {
    const int b = blockIdx.y;
    const int slice = blockIdx.x;
    const float* p1 = pc1 + (size_t)b * 4 * NN;
    const int tid = threadIdx.x;
    const int lane = tid & 31;
    const int w = tid >> 5;

    __shared__ float smW[8];
    __shared__ float smP[8][16];

    float v = g_dpart[b][tid] + g_dpart[b][tid + 256];
    #pragma unroll
    for (int o = 16; o; o >>= 1) v += __shfl_xor_sync(~0u, v, o);
    if (lane == 0) smW[w] = v;
    __syncthreads();
    double ms = 0.0;
    #pragma unroll
    for (int i = 0; i < 8; ++i) ms += (double)smW[i];
    const float mean = (float)(ms * (1.0 / (double)NN));

    float P[16];
    #pragma unroll
    for (int i = 0; i < 16; ++i) P[i] = 0.f;
    #pragma unroll
    for (int k = 0; k < 2; ++k) {
        int n = slice * 512 + k * 256 + tid;
        float dist = g_dist[b][n];
        float z = (dist - mean - kEPS) * 1e10f;
        float ind = 1.0f / (1.0f + __expf(z));
        float axx = p1[n], ayy = p1[NN + n], azz = p1[2 * NN + n];
        float bx = g_pcn[b][0][n], by = g_pcn[b][1][n], bz = g_pcn[b][2][n];
        float iax = ind * axx, iay = ind * ayy, iaz = ind * azz;
        P[0] += ind;
        P[1] += iax; P[2] += iay; P[3] += iaz;
        P[4] += ind * bx; P[5] += ind * by; P[6] += ind * bz;
        P[7]  += iax * bx; P[8]  += iax * by; P[9]  += iax * bz;
        P[10] += iay * bx; P[11] += iay * by; P[12] += iay * bz;
        P[13] += iaz * bx; P[14] += iaz * by; P[15] += iaz * bz;
    }
    #pragma unroll
    for (int o = 16; o; o >>= 1)
        #pragma unroll
        for (int i = 0; i < 16; ++i)
            P[i] += __shfl_xor_sync(~0u, P[i], o);
    if (lane == 0) {
        #pragma unroll
        for (int i = 0; i < 16; ++i) smP[w][i] = P[i];
    }
    __syncthreads();
    if (w == 0 && lane < 16) {
        float s = 0.f;
        #pragma unroll
        for (int ww = 0; ww < 8; ++ww) s += smP[ww][lane];
        g_mpart[b][slice][lane] = s;
    }
}

// ---------------------------------------------------------------------------
// Kernel 4: SVD tail per batch. Lanes 0-15 load the 16 moments in parallel
// (8-deep MLP each), broadcast via shfl; lane 0 runs the serial 3x3 tail.
// ---------------------------------------------------------------------------
__global__ void cpnet_svd(float* __restrict__ out) {
    const int b = blockIdx.x;
    const int lane = threadIdx.x & 31;

    float Sf = 0.f;
    if (lane < 16) {
        #pragma unroll
        for (int sl = 0; sl < 8; ++sl) Sf += g_mpart[b][sl][lane];
    }
    double S[16];
    #pragma unroll
    for (int i = 0; i < 16; ++i)
        S[i] = (double)__shfl_sync(~0u, Sf, i);

    if (threadIdx.x != 0) return;

    const double sw = S[0];
    const double inv_sw = 1.0 / sw;
    float c1v[3] = {(float)(S[1] * inv_sw), (float)(S[2] * inv_sw), (float)(S[3] * inv_sw)};
    float c2v[3] = {(float)(S[4] * inv_sw), (float)(S[5] * inv_sw), (float)(S[6] * inv_sw)};
    float H[3][3];
    #pragma unroll
    for (int i = 0; i < 3; ++i)
        #pragma unroll
        for (int j = 0; j < 3; ++j)
            H[i][j] = (float)(S[7 + i * 3 + j] - S[1 + i] * S[4 + j] * inv_sw);

    float G[3][3];
    #pragma unroll
    for (int i = 0; i < 3; ++i)
        #pragma unroll
        for (int j = 0; j < 3; ++j)
            G[i][j] = H[0][i] * H[0][j] + H[1][i] * H[1][j] + H[2][i] * H[2][j];
    float V[3][3] = {{1, 0, 0}, {0, 1, 0}, {0, 0, 1}};
    const int PP[3] = {0, 0, 1}, QQ[3] = {1, 2, 2};
    #pragma unroll
    for (int it = 0; it < 18; ++it) {
        int p = PP[it % 3], q = QQ[it % 3];
        float apq = G[p][q];
        if (fabsf(apq) > 1e-25f) {
            float theta = (G[q][q] - G[p][p]) / (2.0f * apq);
            float t = copysignf(1.0f, theta) / (fabsf(theta) + sqrtf(theta * theta + 1.0f));
            float c = rsqrtf(t * t + 1.0f);
            float sn = t * c;
            #pragma unroll
            for (int k = 0; k < 3; ++k) {
                float gkp = G[k][p], gkq = G[k][q];
                G[k][p] = c * gkp - sn * gkq;
                G[k][q] = sn * gkp + c * gkq;
            }
            #pragma unroll
            for (int k = 0; k < 3; ++k) {
                float gpk = G[p][k], gqk = G[q][k];
                G[p][k] = c * gpk - sn * gqk;
                G[q][k] = sn * gpk + c * gqk;
            }
            #pragma unroll
            for (int k = 0; k < 3; ++k) {
                float vkp = V[k][p], vkq = V[k][q];
                V[k][p] = c * vkp - sn * vkq;
                V[k][q] = sn * vkp + c * vkq;
            }
        }
    }
    float ev[3] = {G[0][0], G[1][1], G[2][2]};
    #pragma unroll
    for (int a = 0; a < 2; ++a)
        #pragma unroll
        for (int bc = 1; bc < 3; ++bc)
            if (bc > a && ev[bc] > ev[a]) {
                float te = ev[a]; ev[a] = ev[bc]; ev[bc] = te;
                #pragma unroll
                for (int k = 0; k < 3; ++k) {
                    float tv = V[k][a]; V[k][a] = V[k][bc]; V[k][bc] = tv;
                }
            }
    float U[3][3];
    #pragma unroll
    for (int j = 0; j < 3; ++j) {
        float sig = sqrtf(fmaxf(ev[j], 0.f));
        float inv = (sig > 1e-20f) ? (1.0f / sig) : 0.f;
        #pragma unroll
        for (int i = 0; i < 3; ++i)
            U[i][j] = (H[i][0] * V[0][j] + H[i][1] * V[1][j] + H[i][2] * V[2][j]) * inv;
    }
    auto det3 = [](float M[3][3]) {
        return M[0][0] * (M[1][1] * M[2][2] - M[1][2] * M[2][1])
             - M[0][1] * (M[1][0] * M[2][2] - M[1][2] * M[2][0])
             + M[0][2] * (M[1][0] * M[2][1] - M[1][1] * M[2][0]);
    };
    float sign = (det3(U) * det3(V) < 0.f) ? -1.f : 1.f;
    V[0][2] *= sign; V[1][2] *= sign; V[2][2] *= sign;
    float R[3][3];
    #pragma unroll
    for (int i = 0; i < 3; ++i)
        #pragma unroll
        for (int j = 0; j < 3; ++j)
            R[i][j] = V[i][0] * U[j][0] + V[i][1] * U[j][1] + V[i][2] * U[j][2];
    float tt[3];
    #pragma unroll
    for (int i = 0; i < 3; ++i)
        tt[i] = c2v[i] - (R[i][0] * c1v[0] + R[i][1] * c1v[1] + R[i][2] * c1v[2]);

    float* T = out + b * 16;
    #pragma unroll
    for (int i = 0; i < 3; ++i) {
        T[i * 4 + 0] = R[i][0];
        T[i * 4 + 1] = R[i][1];
        T[i * 4 + 2] = R[i][2];
        T[i * 4 + 3] = tt[i];
    }
    T[12] = 0.f; T[13] = 0.f; T[14] = 0.f; T[15] = 1.f;

    auto sgn = [](float x) { return x >= 0.f ? 1.f : -1.f; };
    float qw = 0.5f * sqrtf(fmaxf(1.f + R[0][0] + R[1][1] + R[2][2], 1e-12f));
    float qx = 0.5f * sqrtf(fmaxf(1.f + R[0][0] - R[1][1] - R[2][2], 1e-12f)) * sgn(R[2][1] - R[1][2]);
    float qy = 0.5f * sqrtf(fmaxf(1.f - R[0][0] + R[1][1] - R[2][2], 1e-12f)) * sgn(R[0][2] - R[2][0]);
    float qz = 0.5f * sqrtf(fmaxf(1.f - R[0][0] - R[1][1] + R[2][2], 1e-12f)) * sgn(R[1][0] - R[0][1]);
    float* qo = out + BB * 16 + b * 4;
    qo[0] = qw; qo[1] = qx; qo[2] = qy; qo[3] = qz;
    float* to = out + BB * 16 + BB * 4 + b * 3;
    to[0] = tt[0]; to[1] = tt[1]; to[2] = tt[2];
}

// ---------------------------------------------------------------------------
extern "C" void kernel_launch(void* const* d_in, const int* in_sizes, int n_in,
                              void* d_out, int out_size) {
    const float* pc1 = (const float*)d_in[0];
    const float* pc2 = (const float*)d_in[1];
    float* out = (float*)d_out;

    cpnet_bin<<<BB, 512>>>(pc2);
    dim3 rgrid(RCTAS, BB);   // 512 x 8 CTAs, 8 warps = 8 rows each
    cpnet_rows<<<rgrid, 256>>>(pc1, pc2);
    dim3 mgrid(8, BB);
    cpnet_moments<<<mgrid, 256>>>(pc1);
    cpnet_svd<<<BB, 32>>>(out);
}